// round 3
// baseline (speedup 1.0000x reference)
#include <cuda_runtime.h>
#include <cstdint>

#define NSITES 1000000
#define KVOL 27
#define TPB 256
#define SB 512                                 // sites per block
#define NBLK ((NSITES + SB - 1) / SB)          // 1954
#define EPSV 1e-5f

// ---------------- scratch (device globals; no allocation allowed) ----------
__device__ float d_h1[(size_t)NSITES * 32];    // 128 MB intermediate
__device__ int   d_nmT[(size_t)KVOL * NSITES]; // 108 MB transposed neighbor map
__device__ float d_part[(size_t)NBLK * 64];    // per-block [sum(32), sumsq(32)]
__device__ float d_sb1[64];
__device__ float d_sb2[64];

// ---------------- packed f32x2 helpers -------------------------------------
static __device__ __forceinline__ unsigned long long pack2(float x) {
    unsigned long long r;
    unsigned u = __float_as_uint(x);
    asm("mov.b64 %0, {%1, %1};" : "=l"(r) : "r"(u));
    return r;
}
static __device__ __forceinline__ void fma2(unsigned long long& d,
                                            unsigned long long a,
                                            unsigned long long b) {
    asm("fma.rn.f32x2 %0, %1, %2, %0;" : "+l"(d) : "l"(a), "l"(b));
}
static __device__ __forceinline__ float2 unpack2(unsigned long long v) {
    unsigned lo, hi;
    asm("mov.b64 {%0, %1}, %2;" : "=r"(lo), "=r"(hi) : "l"(v));
    return make_float2(__uint_as_float(lo), __uint_as_float(hi));
}

// ---------------- cp.async helpers -----------------------------------------
static __device__ __forceinline__ void cp16(uint32_t dst, const void* src,
                                            uint32_t srcsize) {
    asm volatile("cp.async.ca.shared.global [%0], [%1], 16, %2;\n"
                 :: "r"(dst), "l"(src), "r"(srcsize));
}
static __device__ __forceinline__ void cp_commit() {
    asm volatile("cp.async.commit_group;\n" ::: "memory");
}
template <int N>
static __device__ __forceinline__ void cp_wait() {
    asm volatile("cp.async.wait_group %0;\n" :: "n"(N) : "memory");
}

// ---------------- neighbor-map transpose ------------------------------------
__global__ __launch_bounds__(TPB) void transpose_nm(const int* __restrict__ nm) {
    __shared__ int tb[TPB * KVOL];
    const int base = blockIdx.x * TPB;
    const int nrows = min(TPB, NSITES - base);
    const int n = nrows * KVOL;
    const long long start = (long long)base * KVOL;
    for (int i = threadIdx.x; i < n; i += TPB) tb[i] = nm[start + i];
    __syncthreads();
    const int t = threadIdx.x;
    if (base + t < NSITES) {
#pragma unroll
        for (int k = 0; k < KVOL; k++)
            d_nmT[(size_t)k * NSITES + base + t] = tb[t * KVOL + k];
    }
}

// ---------------- staged gather-conv (Cout = 32) ----------------------------
// Per k: rows gathered coalesced (cp.async, 128B lines) into padded smem,
// weights (4KB slice) cp.async'd from L2, both double-buffered so k+1 loads
// overlap k compute. Compute: thread owns 2 sites; weights broadcast LDS.128,
// g conflict-free LDS.128 from padded stage rows.
template <int CIN>
__global__ __launch_bounds__(TPB, 2) void conv_kernel(
    const float* __restrict__ X, const float* __restrict__ W,
    float* __restrict__ Y) {
    constexpr int SPAD = CIN + 4;               // 36 or 20 floats (16B-mult, conflict-free)
    constexpr int CH = CIN / 4;                 // float4 chunks per row
    constexpr int REPS = SB * CH / TPB;         // 16 (CIN=32) or 8 (CIN=16)
    constexpr int WCHUNK = CIN * 32 / 4;        // float4 chunks of one weight slice

    extern __shared__ float smem[];
    float* wbuf[2] = {smem, smem + CIN * 32};
    float* stage[2] = {smem + 2 * CIN * 32,
                       smem + 2 * CIN * 32 + SB * SPAD};

    const int t = threadIdx.x;
    const int siteBase = blockIdx.x * SB;
    const int s0 = siteBase + t;
    const int s1 = siteBase + t + TPB;

    // ---- async issue of k-slice into buffer b ----
    auto issue = [&](int k, int b) {
        // weights: one float4 per thread (t < WCHUNK)
        if (t < WCHUNK) {
            uint32_t wdst =
                (uint32_t)__cvta_generic_to_shared(wbuf[b] + t * 4);
            cp16(wdst, W + (size_t)k * CIN * 32 + t * 4, 16);
        }
        // gathered rows
        const int* nmk = d_nmT + (size_t)k * NSITES;
#pragma unroll
        for (int r = 0; r < REPS; r++) {
            const int f = r * TPB + t;
            const int row = f / CH;
            const int ch = f % CH;
            const int gsite = siteBase + row;
            int idx = (gsite < NSITES) ? __ldg(nmk + gsite) : -1;
            const float* src =
                X + ((idx >= 0) ? (size_t)idx * CIN : 0) + ch * 4;
            uint32_t dst = (uint32_t)__cvta_generic_to_shared(
                stage[b] + row * SPAD + ch * 4);
            cp16(dst, src, (idx >= 0) ? 16u : 0u);
        }
    };

    unsigned long long acc0[16], acc1[16];
#pragma unroll
    for (int c = 0; c < 16; c++) {
        acc0[c] = 0ull;
        acc1[c] = 0ull;
    }

    issue(0, 0);
    cp_commit();

#pragma unroll 1
    for (int k = 0; k < KVOL; k++) {
        const int cur = k & 1;
        if (k + 1 < KVOL) {
            issue(k + 1, 1 - cur);
            cp_commit();
            cp_wait<1>();
        } else {
            cp_wait<0>();
        }
        __syncthreads();

        const float* stg = stage[cur];
        const float* wb = wbuf[cur];
#pragma unroll
        for (int ch = 0; ch < CH; ch++) {
            const float4 ga =
                *reinterpret_cast<const float4*>(stg + t * SPAD + ch * 4);
            const float4 gb = *reinterpret_cast<const float4*>(
                stg + (t + TPB) * SPAD + ch * 4);
            const float a4[4] = {ga.x, ga.y, ga.z, ga.w};
            const float b4[4] = {gb.x, gb.y, gb.z, gb.w};
#pragma unroll
            for (int j = 0; j < 4; j++) {
                const unsigned long long gv0 = pack2(a4[j]);
                const unsigned long long gv1 = pack2(b4[j]);
                const ulonglong2* wp = reinterpret_cast<const ulonglong2*>(
                    wb + (ch * 4 + j) * 32);
#pragma unroll
                for (int c = 0; c < 8; c++) {
                    const ulonglong2 w = wp[c];
                    fma2(acc0[2 * c + 0], w.x, gv0);
                    fma2(acc0[2 * c + 1], w.y, gv0);
                    fma2(acc1[2 * c + 0], w.x, gv1);
                    fma2(acc1[2 * c + 1], w.y, gv1);
                }
            }
        }
        __syncthreads();
    }

    // ---- unpack, mask tail, store, fold BN partials ----
    float sv[32], qv[32];
    {
        float av[32], bv[32];
#pragma unroll
        for (int c = 0; c < 16; c++) {
            float2 f0 = unpack2(acc0[c]);
            av[2 * c + 0] = f0.x;
            av[2 * c + 1] = f0.y;
            float2 f1 = unpack2(acc1[c]);
            bv[2 * c + 0] = f1.x;
            bv[2 * c + 1] = f1.y;
        }
        if (s0 >= NSITES) {
#pragma unroll
            for (int c = 0; c < 32; c++) av[c] = 0.f;
        }
        if (s1 >= NSITES) {
#pragma unroll
            for (int c = 0; c < 32; c++) bv[c] = 0.f;
        }
        if (s0 < NSITES) {
            float4* y = reinterpret_cast<float4*>(Y + (size_t)s0 * 32);
#pragma unroll
            for (int c = 0; c < 8; c++)
                y[c] = make_float4(av[4 * c], av[4 * c + 1], av[4 * c + 2],
                                   av[4 * c + 3]);
        }
        if (s1 < NSITES) {
            float4* y = reinterpret_cast<float4*>(Y + (size_t)s1 * 32);
#pragma unroll
            for (int c = 0; c < 8; c++)
                y[c] = make_float4(bv[4 * c], bv[4 * c + 1], bv[4 * c + 2],
                                   bv[4 * c + 3]);
        }
#pragma unroll
        for (int c = 0; c < 32; c++) {
            sv[c] = av[c] + bv[c];
            qv[c] = av[c] * av[c] + bv[c] * bv[c];
        }
    }

    __syncthreads();  // stage no longer needed; reuse for reduction
    const int lane = t & 31;
    const int wrp = t >> 5;
#pragma unroll
    for (int c = 0; c < 32; c++) {
        float s = sv[c];
        float q = qv[c];
#pragma unroll
        for (int o = 16; o > 0; o >>= 1) {
            s += __shfl_down_sync(0xffffffffu, s, o);
            q += __shfl_down_sync(0xffffffffu, q, o);
        }
        if (lane == 0) {
            smem[wrp * 64 + c] = s;
            smem[wrp * 64 + 32 + c] = q;
        }
    }
    __syncthreads();
    if (t < 64) {
        float s = 0.f;
#pragma unroll
        for (int w = 0; w < 8; w++) s += smem[w * 64 + t];
        d_part[(size_t)blockIdx.x * 64 + t] = s;
    }
}

// ---------------- finalize BN stats -> scale/bias --------------------------
__global__ void finalize_kernel(const float* __restrict__ gamma,
                                const float* __restrict__ beta,
                                float* __restrict__ sb, int nb) {
    const int c = blockIdx.x;  // 0..31
    float s = 0.f, q = 0.f;
    for (int b = threadIdx.x; b < nb; b += 256) {
        s += d_part[(size_t)b * 64 + c];
        q += d_part[(size_t)b * 64 + 32 + c];
    }
    __shared__ float ss[8], qs[8];
    const int lane = threadIdx.x & 31;
    const int wrp = threadIdx.x >> 5;
#pragma unroll
    for (int o = 16; o > 0; o >>= 1) {
        s += __shfl_down_sync(0xffffffffu, s, o);
        q += __shfl_down_sync(0xffffffffu, q, o);
    }
    if (lane == 0) {
        ss[wrp] = s;
        qs[wrp] = q;
    }
    __syncthreads();
    if (threadIdx.x == 0) {
        float S = 0.f, Q = 0.f;
#pragma unroll
        for (int w = 0; w < 8; w++) {
            S += ss[w];
            Q += qs[w];
        }
        const float inv_n = 1.0f / (float)NSITES;
        float mean = S * inv_n;
        float var = Q * inv_n - mean * mean;
        float scale = gamma[c] * rsqrtf(var + EPSV);
        sb[c] = scale;
        sb[32 + c] = beta[c] - mean * scale;
    }
}

// ---------------- in-place BN + ReLU ---------------------------------------
__global__ __launch_bounds__(256) void bnrelu_kernel(float* __restrict__ Y,
                                                     const float* __restrict__ sb) {
    __shared__ float sc[32], bi[32];
    if (threadIdx.x < 32) {
        sc[threadIdx.x] = sb[threadIdx.x];
        bi[threadIdx.x] = sb[32 + threadIdx.x];
    }
    __syncthreads();
    const long long i = (long long)blockIdx.x * 256 + threadIdx.x;  // float4 idx
    float4* p = reinterpret_cast<float4*>(Y);
    float4 v = p[i];
    const int c0 = (int)((i * 4) & 31);
    v.x = fmaxf(0.f, fmaf(v.x, sc[c0 + 0], bi[c0 + 0]));
    v.y = fmaxf(0.f, fmaf(v.y, sc[c0 + 1], bi[c0 + 1]));
    v.z = fmaxf(0.f, fmaf(v.z, sc[c0 + 2], bi[c0 + 2]));
    v.w = fmaxf(0.f, fmaf(v.w, sc[c0 + 3], bi[c0 + 3]));
    p[i] = v;
}

// ---------------- launch ----------------------------------------------------
extern "C" void kernel_launch(void* const* d_in, const int* in_sizes, int n_in,
                              void* d_out, int out_size) {
    const float* feats = (const float*)d_in[0];
    const int* nm = (const int*)d_in[1];
    const float* W1 = (const float*)d_in[2];
    const float* gamma1 = (const float*)d_in[3];
    const float* beta1 = (const float*)d_in[4];
    const float* W2 = (const float*)d_in[5];
    const float* gamma2 = (const float*)d_in[6];
    const float* beta2 = (const float*)d_in[7];
    float* out = (float*)d_out;

    // smem: 2 weight slices + 2 padded stage buffers
    const int smem1 = (2 * 16 * 32 + 2 * SB * 20) * (int)sizeof(float);  //  86016
    const int smem2 = (2 * 32 * 32 + 2 * SB * 36) * (int)sizeof(float);  // 155648
    cudaFuncSetAttribute(conv_kernel<16>,
                         cudaFuncAttributeMaxDynamicSharedMemorySize, smem1);
    cudaFuncSetAttribute(conv_kernel<32>,
                         cudaFuncAttributeMaxDynamicSharedMemorySize, smem2);

    void* h1p = nullptr;
    cudaGetSymbolAddress(&h1p, d_h1);
    float* h1 = (float*)h1p;
    void* sb1p = nullptr;
    cudaGetSymbolAddress(&sb1p, d_sb1);
    float* sb1 = (float*)sb1p;
    void* sb2p = nullptr;
    cudaGetSymbolAddress(&sb2p, d_sb2);
    float* sb2 = (float*)sb2p;

    const int ew_blocks = (int)(((long long)NSITES * 32 / 4) / 256);  // 31250
    const int tr_blocks = (NSITES + TPB - 1) / TPB;                   // 3907

    transpose_nm<<<tr_blocks, TPB>>>(nm);
    conv_kernel<16><<<NBLK, TPB, smem1>>>(feats, W1, h1);
    finalize_kernel<<<32, 256>>>(gamma1, beta1, sb1, NBLK);
    bnrelu_kernel<<<ew_blocks, 256>>>(h1, sb1);
    conv_kernel<32><<<NBLK, TPB, smem2>>>(h1, W2, out);
    finalize_kernel<<<32, 256>>>(gamma2, beta2, sb2, NBLK);
    bnrelu_kernel<<<ew_blocks, 256>>>(out, sb2);
}

// round 7
// speedup vs baseline: 1.9129x; 1.9129x over previous
#include <cuda_runtime.h>
#include <cstdint>

#define NSITES 1000000
#define KVOL 27
#define MTILE 128
#define NTILES ((NSITES + MTILE - 1) / MTILE)  // 7813
#define EPSV 1e-5f

// ---------------- scratch (device globals; no allocation allowed) ----------
__device__ float d_h1[(size_t)NSITES * 32];   // conv1 output / conv2 input
__device__ float d_xt[(size_t)NSITES * 16];   // tf32-truncated feats
__device__ int d_nmT[(size_t)KVOL * NSITES];  // transposed neighbor map
__device__ float d_wT1[KVOL * 16 * 32];       // WT[k][cout][cin], tf32-truncated
__device__ float d_wT2[KVOL * 32 * 32];
__device__ float d_part[(size_t)NTILES * 64]; // per-tile [sum(32), sumsq(32)]
__device__ float d_sb1[64];
__device__ float d_sb2[64];

// ---------------- helpers ---------------------------------------------------
static __device__ __forceinline__ uint32_t s2u(const void* p) {
    return (uint32_t)__cvta_generic_to_shared(p);
}
static __device__ __forceinline__ void cp16(uint32_t dst, const void* src,
                                            uint32_t srcsize) {
    asm volatile("cp.async.ca.shared.global [%0], [%1], 16, %2;\n" ::"r"(dst),
                 "l"(src), "r"(srcsize));
}
static __device__ __forceinline__ void cp_commit() {
    asm volatile("cp.async.commit_group;\n" ::: "memory");
}
template <int N>
static __device__ __forceinline__ void cp_wait() {
    asm volatile("cp.async.wait_group %0;\n" ::"n"(N) : "memory");
}
static __device__ __forceinline__ uint32_t f2tf32(float f) {
    uint32_t u;
    asm("cvt.rna.tf32.f32 %0, %1;" : "=r"(u) : "f"(f));
    return u;
}
// mma.sync m16n8k8 tf32: D(16x8,f32) += A(16x8,row) * B(8x8,col)
static __device__ __forceinline__ void mma_tf32(float* d, uint32_t a0,
                                                uint32_t a1, uint32_t a2,
                                                uint32_t a3, uint32_t b0,
                                                uint32_t b1) {
    asm volatile(
        "mma.sync.aligned.m16n8k8.row.col.f32.tf32.tf32.f32 "
        "{%0,%1,%2,%3},{%4,%5,%6,%7},{%8,%9},{%0,%1,%2,%3};"
        : "+f"(d[0]), "+f"(d[1]), "+f"(d[2]), "+f"(d[3])
        : "r"(a0), "r"(a1), "r"(a2), "r"(a3), "r"(b0), "r"(b1));
}

// ---------------- neighbor-map transpose ------------------------------------
__global__ __launch_bounds__(256) void transpose_nm(const int* __restrict__ nm) {
    __shared__ int tb[256 * KVOL];
    const int base = blockIdx.x * 256;
    const int nrows = min(256, NSITES - base);
    const int n = nrows * KVOL;
    const long long start = (long long)base * KVOL;
    for (int i = threadIdx.x; i < n; i += 256) tb[i] = nm[start + i];
    __syncthreads();
    const int t = threadIdx.x;
    if (base + t < NSITES) {
#pragma unroll
        for (int k = 0; k < KVOL; k++)
            d_nmT[(size_t)k * NSITES + base + t] = tb[t * KVOL + k];
    }
}

// ---------------- input truncation to tf32 ----------------------------------
__global__ __launch_bounds__(256) void prep_x(const float* __restrict__ X) {
    const long long i = (long long)blockIdx.x * 256 + threadIdx.x;  // float4 idx
    const float4 v = reinterpret_cast<const float4*>(X)[i];
    float4 o;
    o.x = __uint_as_float(f2tf32(v.x));
    o.y = __uint_as_float(f2tf32(v.y));
    o.z = __uint_as_float(f2tf32(v.z));
    o.w = __uint_as_float(f2tf32(v.w));
    reinterpret_cast<float4*>(d_xt)[i] = o;
}

// ---------------- weight transpose + truncate --------------------------------
// W[k][cin][cout] -> WT[k][cout][cin] (tf32-truncated)
__global__ void prep_w(const float* __restrict__ W, float* __restrict__ dst,
                       int cin) {
    const int k = blockIdx.x;
    for (int e = threadIdx.x; e < cin * 32; e += 256) {
        const int i = e / 32;
        const int c = e % 32;
        dst[((size_t)k * 32 + c) * cin + i] =
            __uint_as_float(f2tf32(W[((size_t)k * cin + i) * 32 + c]));
    }
}

// ---------------- mma.sync gather-conv ---------------------------------------
// 128 thr / 4 warps; warp w: sites [w*32, w*32+32) x all 32 couts.
// Double-buffered cp.async staging; padded stride CIN+4 -> conflict-free LDS.
template <int CIN>
__global__ __launch_bounds__(128) void conv_mma(const float* __restrict__ X,
                                                const float* __restrict__ WT,
                                                float* __restrict__ Y) {
    constexpr int NK = CIN / 8;   // K-steps per offset
    constexpr int CH = CIN / 4;   // 16B chunks per row
    constexpr int STR = CIN + 4;  // padded row stride (floats)

    extern __shared__ float smem[];
    float* const A[2] = {smem, smem + 128 * STR};
    float* const B[2] = {smem + 256 * STR, smem + 256 * STR + 32 * STR};
    float* const red = smem;  // reused post-loop

    const int t = threadIdx.x;
    const int w = t >> 5;
    const int lane = t & 31;
    const int g = lane >> 2;   // groupID
    const int ti = lane & 3;   // thread-in-group
    const int siteBase = blockIdx.x * MTILE;

    auto issue = [&](int k, int b) {
        // B: WT slice [32][CIN] -> padded rows
        const float* wsrc = WT + (size_t)k * CIN * 32;
#pragma unroll
        for (int c = t; c < 32 * CH; c += 128) {
            const int row = c / CH;
            const int ch = c % CH;
            cp16(s2u(B[b] + row * STR + ch * 4), wsrc + c * 4, 16);
        }
        // A: one gathered row per thread (contiguous 16B chunks)
        const int* nmk = d_nmT + (size_t)k * NSITES;
        const int gsite = siteBase + t;
        const int idx = (gsite < NSITES) ? nmk[gsite] : -1;
        const float* src = X + ((idx >= 0) ? (size_t)idx * CIN : 0);
        const uint32_t dst = s2u(A[b] + t * STR);
        const uint32_t sz = (idx >= 0) ? 16u : 0u;
#pragma unroll
        for (int ch = 0; ch < CH; ch++) cp16(dst + ch * 16, src + ch * 4, sz);
    };

    float acc[2][4][4];
#pragma unroll
    for (int m = 0; m < 2; m++)
#pragma unroll
        for (int n = 0; n < 4; n++)
#pragma unroll
            for (int r = 0; r < 4; r++) acc[m][n][r] = 0.f;

    issue(0, 0);
    cp_commit();
    issue(1, 1);
    cp_commit();

#pragma unroll 1
    for (int k = 0; k < KVOL; k++) {
        const int b = k & 1;
        if (k < KVOL - 1)
            cp_wait<1>();
        else
            cp_wait<0>();
        __syncthreads();

        const float* As = A[b];
        const float* Bs = B[b];
#pragma unroll
        for (int ks = 0; ks < NK; ks++) {
            uint32_t bf[4][2];
#pragma unroll
            for (int n = 0; n < 4; n++) {
                const uint32_t* bp = reinterpret_cast<const uint32_t*>(
                    Bs + (n * 8 + g) * STR + ks * 8 + ti);
                bf[n][0] = bp[0];
                bf[n][1] = bp[4];
            }
#pragma unroll
            for (int m = 0; m < 2; m++) {
                const uint32_t* ap = reinterpret_cast<const uint32_t*>(
                    As + (w * 32 + m * 16 + g) * STR + ks * 8 + ti);
                const uint32_t a0 = ap[0];
                const uint32_t a2 = ap[4];
                const uint32_t* ap1 = ap + 8 * STR;
                const uint32_t a1 = ap1[0];
                const uint32_t a3 = ap1[4];
#pragma unroll
                for (int n = 0; n < 4; n++)
                    mma_tf32(acc[m][n], a0, a1, a2, a3, bf[n][0], bf[n][1]);
            }
        }
        __syncthreads();
        if (k + 2 < KVOL) {
            issue(k + 2, b);
            cp_commit();
        }
    }

    // ---- store: thread holds rows {m*16+g, m*16+g+8}, cols {n*8+2ti, +1} ----
#pragma unroll
    for (int m = 0; m < 2; m++)
#pragma unroll
        for (int rr = 0; rr < 2; rr++) {
            const int row = w * 32 + m * 16 + rr * 8 + g;
            const int site = siteBase + row;
            if (site < NSITES) {
                float* yr = Y + (size_t)site * 32 + 2 * ti;
#pragma unroll
                for (int n = 0; n < 4; n++) {
                    float2 v =
                        make_float2(acc[m][n][rr * 2], acc[m][n][rr * 2 + 1]);
                    *reinterpret_cast<float2*>(yr + n * 8) = v;
                }
            }
        }

    // ---- BN partial stats (tail rows are zero by construction) ----
    float s[8], q[8];
#pragma unroll
    for (int i = 0; i < 8; i++) {
        s[i] = 0.f;
        q[i] = 0.f;
    }
#pragma unroll
    for (int m = 0; m < 2; m++)
#pragma unroll
        for (int n = 0; n < 4; n++)
#pragma unroll
            for (int rr = 0; rr < 2; rr++)
#pragma unroll
                for (int e = 0; e < 2; e++) {
                    const float v = acc[m][n][rr * 2 + e];
                    s[n * 2 + e] += v;
                    q[n * 2 + e] += v * v;
                }
    // reduce across g (lanes differing in bits 2..4)
#pragma unroll
    for (int i = 0; i < 8; i++) {
#pragma unroll
        for (int o = 4; o <= 16; o <<= 1) {
            s[i] += __shfl_xor_sync(0xffffffffu, s[i], o);
            q[i] += __shfl_xor_sync(0xffffffffu, q[i], o);
        }
    }
    __syncthreads();  // smem free (stage buffers no longer needed)
    if (g == 0) {
#pragma unroll
        for (int i = 0; i < 8; i++) {
            const int col = (i / 2) * 8 + 2 * ti + (i % 2);
            red[w * 64 + col] = s[i];
            red[w * 64 + 32 + col] = q[i];
        }
    }
    __syncthreads();
    if (t < 64) {
        float ss = 0.f;
#pragma unroll
        for (int wi = 0; wi < 4; wi++) ss += red[wi * 64 + t];
        d_part[(size_t)blockIdx.x * 64 + t] = ss;
    }
}

// ---------------- finalize BN stats -> scale/bias --------------------------
__global__ void finalize_kernel(const float* __restrict__ gamma,
                                const float* __restrict__ beta,
                                float* __restrict__ sb, int nb) {
    const int c = blockIdx.x;  // 0..31
    float s = 0.f, q = 0.f;
    for (int b = threadIdx.x; b < nb; b += 256) {
        s += d_part[(size_t)b * 64 + c];
        q += d_part[(size_t)b * 64 + 32 + c];
    }
    __shared__ float ss[8], qs[8];
    const int lane = threadIdx.x & 31;
    const int wrp = threadIdx.x >> 5;
#pragma unroll
    for (int o = 16; o > 0; o >>= 1) {
        s += __shfl_down_sync(0xffffffffu, s, o);
        q += __shfl_down_sync(0xffffffffu, q, o);
    }
    if (lane == 0) {
        ss[wrp] = s;
        qs[wrp] = q;
    }
    __syncthreads();
    if (threadIdx.x == 0) {
        float S = 0.f, Q = 0.f;
#pragma unroll
        for (int w = 0; w < 8; w++) {
            S += ss[w];
            Q += qs[w];
        }
        const float inv_n = 1.0f / (float)NSITES;
        float mean = S * inv_n;
        float var = Q * inv_n - mean * mean;
        float scale = gamma[c] * rsqrtf(var + EPSV);
        sb[c] = scale;
        sb[32 + c] = beta[c] - mean * scale;
    }
}

// ---------------- in-place BN + ReLU (optionally tf32-truncating) -----------
template <int TRUNC>
__global__ __launch_bounds__(256) void bnrelu_kernel(float* __restrict__ Y,
                                                     const float* __restrict__ sb) {
    __shared__ float sc[32], bi[32];
    if (threadIdx.x < 32) {
        sc[threadIdx.x] = sb[threadIdx.x];
        bi[threadIdx.x] = sb[32 + threadIdx.x];
    }
    __syncthreads();
    const long long i = (long long)blockIdx.x * 256 + threadIdx.x;  // float4 idx
    float4* p = reinterpret_cast<float4*>(Y);
    float4 v = p[i];
    const int c0 = (int)((i * 4) & 31);
    v.x = fmaxf(0.f, fmaf(v.x, sc[c0 + 0], bi[c0 + 0]));
    v.y = fmaxf(0.f, fmaf(v.y, sc[c0 + 1], bi[c0 + 1]));
    v.z = fmaxf(0.f, fmaf(v.z, sc[c0 + 2], bi[c0 + 2]));
    v.w = fmaxf(0.f, fmaf(v.w, sc[c0 + 3], bi[c0 + 3]));
    if (TRUNC) {
        v.x = __uint_as_float(f2tf32(v.x));
        v.y = __uint_as_float(f2tf32(v.y));
        v.z = __uint_as_float(f2tf32(v.z));
        v.w = __uint_as_float(f2tf32(v.w));
    }
    p[i] = v;
}

// ---------------- launch ----------------------------------------------------
extern "C" void kernel_launch(void* const* d_in, const int* in_sizes, int n_in,
                              void* d_out, int out_size) {
    const float* feats = (const float*)d_in[0];
    const int* nm = (const int*)d_in[1];
    const float* W1 = (const float*)d_in[2];
    const float* gamma1 = (const float*)d_in[3];
    const float* beta1 = (const float*)d_in[4];
    const float* W2 = (const float*)d_in[5];
    const float* gamma2 = (const float*)d_in[6];
    const float* beta2 = (const float*)d_in[7];
    float* out = (float*)d_out;

    const int smem1 = (2 * 128 * 20 + 2 * 32 * 20) * 4;  // 25600 B
    const int smem2 = (2 * 128 * 36 + 2 * 32 * 36) * 4;  // 46080 B
    cudaFuncSetAttribute(conv_mma<16>,
                         cudaFuncAttributeMaxDynamicSharedMemorySize, smem1);
    cudaFuncSetAttribute(conv_mma<32>,
                         cudaFuncAttributeMaxDynamicSharedMemorySize, smem2);

    void* p;
    cudaGetSymbolAddress(&p, d_h1);
    float* h1 = (float*)p;
    cudaGetSymbolAddress(&p, d_xt);
    float* xt = (float*)p;
    cudaGetSymbolAddress(&p, d_wT1);
    float* wT1 = (float*)p;
    cudaGetSymbolAddress(&p, d_wT2);
    float* wT2 = (float*)p;
    cudaGetSymbolAddress(&p, d_sb1);
    float* sb1 = (float*)p;
    cudaGetSymbolAddress(&p, d_sb2);
    float* sb2 = (float*)p;

    const int ew_blocks = (int)(((long long)NSITES * 32 / 4) / 256);  // 31250
    const int tr_blocks = (NSITES + 255) / 256;                       // 3907
    const int px_blocks = (int)(((long long)NSITES * 16 / 4) / 256);  // 15625

    transpose_nm<<<tr_blocks, 256>>>(nm);
    prep_x<<<px_blocks, 256>>>(feats);
    prep_w<<<KVOL, 256>>>(W1, wT1, 16);
    prep_w<<<KVOL, 256>>>(W2, wT2, 32);

    conv_mma<16><<<NTILES, 128, smem1>>>(xt, wT1, h1);
    finalize_kernel<<<32, 256>>>(gamma1, beta1, sb1, NTILES);
    bnrelu_kernel<1><<<ew_blocks, 256>>>(h1, sb1);  // truncate for conv2 input

    conv_mma<32><<<NTILES, 128, smem2>>>(h1, wT2, out);
    finalize_kernel<<<32, 256>>>(gamma2, beta2, sb2, NTILES);
    bnrelu_kernel<0><<<ew_blocks, 256>>>(out, sb2);
}

// round 9
// speedup vs baseline: 2.0168x; 1.0543x over previous
#include <cuda_runtime.h>
#include <cstdint>

#define NSITES 1000000
#define KVOL 27
#define MTILE 128
#define NTILES ((NSITES + MTILE - 1) / MTILE)  // 7813
#define EPSV 1e-5f

// ---------------- scratch (device globals; no allocation allowed) ----------
__device__ float d_h1[(size_t)NSITES * 32];   // conv1 output / conv2 input
__device__ float d_xt[(size_t)NSITES * 16];   // tf32-truncated feats
__device__ int d_nmT[(size_t)KVOL * NSITES];  // transposed neighbor map
__device__ float d_wT1[KVOL * 16 * 32];       // WT[k][cout][cin], tf32-truncated
__device__ float d_wT2[KVOL * 32 * 32];
__device__ float d_part[(size_t)NTILES * 64]; // per-tile [sum(32), sumsq(32)]
__device__ float d_sb1[64];
__device__ float d_sb2[64];

// ---------------- helpers ---------------------------------------------------
static __device__ __forceinline__ uint32_t s2u(const void* p) {
    return (uint32_t)__cvta_generic_to_shared(p);
}
static __device__ __forceinline__ void cp16(uint32_t dst, const void* src,
                                            uint32_t srcsize) {
    asm volatile("cp.async.ca.shared.global [%0], [%1], 16, %2;\n" ::"r"(dst),
                 "l"(src), "r"(srcsize));
}
static __device__ __forceinline__ void cp_commit() {
    asm volatile("cp.async.commit_group;\n" ::: "memory");
}
template <int N>
static __device__ __forceinline__ void cp_wait() {
    asm volatile("cp.async.wait_group %0;\n" ::"n"(N) : "memory");
}
static __device__ __forceinline__ uint32_t f2tf32(float f) {
    uint32_t u;
    asm("cvt.rna.tf32.f32 %0, %1;" : "=r"(u) : "f"(f));
    return u;
}
// mma.sync m16n8k8 tf32: D(16x8,f32) += A(16x8,row) * B(8x8,col)
static __device__ __forceinline__ void mma_tf32(float* d, uint32_t a0,
                                                uint32_t a1, uint32_t a2,
                                                uint32_t a3, uint32_t b0,
                                                uint32_t b1) {
    asm volatile(
        "mma.sync.aligned.m16n8k8.row.col.f32.tf32.tf32.f32 "
        "{%0,%1,%2,%3},{%4,%5,%6,%7},{%8,%9},{%0,%1,%2,%3};"
        : "+f"(d[0]), "+f"(d[1]), "+f"(d[2]), "+f"(d[3])
        : "r"(a0), "r"(a1), "r"(a2), "r"(a3), "r"(b0), "r"(b1));
}
// ldmatrix x4: four 8-row x 16B submatrices; lane l supplies row address of
// submatrix l/8, receives word (l%4) of row (l/4) of each submatrix.
static __device__ __forceinline__ void ldsm4(uint32_t& r0, uint32_t& r1,
                                             uint32_t& r2, uint32_t& r3,
                                             uint32_t addr) {
    asm volatile(
        "ldmatrix.sync.aligned.m8n8.x4.shared.b16 {%0,%1,%2,%3}, [%4];"
        : "=r"(r0), "=r"(r1), "=r"(r2), "=r"(r3)
        : "r"(addr));
}

// ---------------- neighbor-map transpose ------------------------------------
__global__ __launch_bounds__(256) void transpose_nm(const int* __restrict__ nm) {
    __shared__ int tb[256 * KVOL];
    const int base = blockIdx.x * 256;
    const int nrows = min(256, NSITES - base);
    const int n = nrows * KVOL;
    const long long start = (long long)base * KVOL;
    for (int i = threadIdx.x; i < n; i += 256) tb[i] = nm[start + i];
    __syncthreads();
    const int t = threadIdx.x;
    if (base + t < NSITES) {
#pragma unroll
        for (int k = 0; k < KVOL; k++)
            d_nmT[(size_t)k * NSITES + base + t] = tb[t * KVOL + k];
    }
}

// ---------------- input truncation to tf32 ----------------------------------
__global__ __launch_bounds__(256) void prep_x(const float* __restrict__ X) {
    const long long i = (long long)blockIdx.x * 256 + threadIdx.x;  // float4 idx
    const float4 v = reinterpret_cast<const float4*>(X)[i];
    float4 o;
    o.x = __uint_as_float(f2tf32(v.x));
    o.y = __uint_as_float(f2tf32(v.y));
    o.z = __uint_as_float(f2tf32(v.z));
    o.w = __uint_as_float(f2tf32(v.w));
    reinterpret_cast<float4*>(d_xt)[i] = o;
}

// ---------------- weight transpose + truncate --------------------------------
// W[k][cin][cout] -> WT[k][cout][cin] (tf32-truncated)
__global__ void prep_w(const float* __restrict__ W, float* __restrict__ dst,
                       int cin) {
    const int k = blockIdx.x;
    for (int e = threadIdx.x; e < cin * 32; e += 256) {
        const int i = e / 32;
        const int c = e % 32;
        dst[((size_t)k * 32 + c) * cin + i] =
            __uint_as_float(f2tf32(W[((size_t)k * cin + i) * 32 + c]));
    }
}

// ---------------- mma.sync gather-conv ---------------------------------------
// 128 thr / 4 warps; warp w: sites [w*32, w*32+32) x all 32 couts.
// Double-buffered cp.async staging; fragment loads via ldmatrix.x4
// (byte-identical distribution to the scalar loads, 6x fewer instructions).
template <int CIN>
__global__ __launch_bounds__(128) void conv_mma(const float* __restrict__ X,
                                                const float* __restrict__ WT,
                                                float* __restrict__ Y) {
    constexpr int NK = CIN / 8;        // K-steps per offset
    constexpr int CH = CIN / 4;        // 16B chunks per row
    constexpr int STR = CIN + 4;       // padded row stride (floats)
    constexpr int STR4 = STR * 4;      // bytes

    extern __shared__ float smem[];
    float* const A[2] = {smem, smem + 128 * STR};
    float* const B[2] = {smem + 256 * STR, smem + 256 * STR + 32 * STR};
    float* const red = smem;  // reused post-loop

    const int t = threadIdx.x;
    const int w = t >> 5;
    const int lane = t & 31;
    const int g = lane >> 2;   // groupID
    const int ti = lane & 3;   // thread-in-group
    const int siteBase = blockIdx.x * MTILE;

    // ldmatrix per-lane base offsets (bytes)
    const int lr = lane & 7;
    const int sel = lane >> 3;
    // A: submatrices {rows m16+0-7,k0-3},{+8,k0-3},{0-7,k4-7},{+8,k4-7}
    const uint32_t aoff =
        (uint32_t)((w * 32 + ((sel & 1) * 8) + lr) * STR4 + ((sel & 2) ? 16 : 0));
    // B: submatrices {rows n8+0-7,k0-3},{n8,k4-7},{n8+8,k0-3},{n8+8,k4-7}
    const uint32_t boff =
        (uint32_t)((((sel >> 1) & 1) * 8 + lr) * STR4 + ((sel & 1) * 16));

    auto issue = [&](int k, int b) {
        // B: WT slice [32][CIN] -> padded rows
        const float* wsrc = WT + (size_t)k * CIN * 32;
#pragma unroll
        for (int c = t; c < 32 * CH; c += 128) {
            const int row = c / CH;
            const int ch = c % CH;
            cp16(s2u(B[b] + row * STR + ch * 4), wsrc + c * 4, 16);
        }
        // A: one gathered row per thread (contiguous 16B chunks)
        const int* nmk = d_nmT + (size_t)k * NSITES;
        const int gsite = siteBase + t;
        const int idx = (gsite < NSITES) ? nmk[gsite] : -1;
        const float* src = X + ((idx >= 0) ? (size_t)idx * CIN : 0);
        const uint32_t dst = s2u(A[b] + t * STR);
        const uint32_t sz = (idx >= 0) ? 16u : 0u;
#pragma unroll
        for (int ch = 0; ch < CH; ch++) cp16(dst + ch * 16, src + ch * 4, sz);
    };

    float acc[2][4][4];
#pragma unroll
    for (int m = 0; m < 2; m++)
#pragma unroll
        for (int n = 0; n < 4; n++)
#pragma unroll
            for (int r = 0; r < 4; r++) acc[m][n][r] = 0.f;

    issue(0, 0);
    cp_commit();
    issue(1, 1);
    cp_commit();

#pragma unroll 1
    for (int k = 0; k < KVOL; k++) {
        const int b = k & 1;
        if (k < KVOL - 1)
            cp_wait<1>();
        else
            cp_wait<0>();
        __syncthreads();

        const uint32_t abase = s2u(A[b]) + aoff;
        const uint32_t bbase = s2u(B[b]) + boff;
#pragma unroll
        for (int ks = 0; ks < NK; ks++) {
            uint32_t bf[4][2];
            ldsm4(bf[0][0], bf[0][1], bf[1][0], bf[1][1],
                  bbase + (uint32_t)(ks * 32));
            ldsm4(bf[2][0], bf[2][1], bf[3][0], bf[3][1],
                  bbase + (uint32_t)(16 * STR4 + ks * 32));
#pragma unroll
            for (int m = 0; m < 2; m++) {
                uint32_t a0, a1, a2, a3;
                ldsm4(a0, a1, a2, a3,
                      abase + (uint32_t)(m * 16 * STR4 + ks * 32));
#pragma unroll
                for (int n = 0; n < 4; n++)
                    mma_tf32(acc[m][n], a0, a1, a2, a3, bf[n][0], bf[n][1]);
            }
        }
        __syncthreads();
        if (k + 2 < KVOL) {
            issue(k + 2, b);
            cp_commit();
        }
    }

    // ---- store: thread holds rows {m*16+g, m*16+g+8}, cols {n*8+2ti, +1} ----
#pragma unroll
    for (int m = 0; m < 2; m++)
#pragma unroll
        for (int rr = 0; rr < 2; rr++) {
            const int row = w * 32 + m * 16 + rr * 8 + g;
            const int site = siteBase + row;
            if (site < NSITES) {
                float* yr = Y + (size_t)site * 32 + 2 * ti;
#pragma unroll
                for (int n = 0; n < 4; n++) {
                    float2 v =
                        make_float2(acc[m][n][rr * 2], acc[m][n][rr * 2 + 1]);
                    *reinterpret_cast<float2*>(yr + n * 8) = v;
                }
            }
        }

    // ---- BN partial stats (tail rows are zero by construction) ----
    float s[8], q[8];
#pragma unroll
    for (int i = 0; i < 8; i++) {
        s[i] = 0.f;
        q[i] = 0.f;
    }
#pragma unroll
    for (int m = 0; m < 2; m++)
#pragma unroll
        for (int n = 0; n < 4; n++)
#pragma unroll
            for (int rr = 0; rr < 2; rr++)
#pragma unroll
                for (int e = 0; e < 2; e++) {
                    const float v = acc[m][n][rr * 2 + e];
                    s[n * 2 + e] += v;
                    q[n * 2 + e] += v * v;
                }
    // reduce across g (lanes differing in bits 2..4)
#pragma unroll
    for (int i = 0; i < 8; i++) {
#pragma unroll
        for (int o = 4; o <= 16; o <<= 1) {
            s[i] += __shfl_xor_sync(0xffffffffu, s[i], o);
            q[i] += __shfl_xor_sync(0xffffffffu, q[i], o);
        }
    }
    __syncthreads();  // smem free (stage buffers no longer needed)
    if (g == 0) {
#pragma unroll
        for (int i = 0; i < 8; i++) {
            const int col = (i / 2) * 8 + 2 * ti + (i % 2);
            red[w * 64 + col] = s[i];
            red[w * 64 + 32 + col] = q[i];
        }
    }
    __syncthreads();
    if (t < 64) {
        float ss = 0.f;
#pragma unroll
        for (int wi = 0; wi < 4; wi++) ss += red[wi * 64 + t];
        d_part[(size_t)blockIdx.x * 64 + t] = ss;
    }
}

// ---------------- finalize BN stats -> scale/bias --------------------------
__global__ void finalize_kernel(const float* __restrict__ gamma,
                                const float* __restrict__ beta,
                                float* __restrict__ sb, int nb) {
    const int c = blockIdx.x;  // 0..31
    float s = 0.f, q = 0.f;
    for (int b = threadIdx.x; b < nb; b += 256) {
        s += d_part[(size_t)b * 64 + c];
        q += d_part[(size_t)b * 64 + 32 + c];
    }
    __shared__ float ss[8], qs[8];
    const int lane = threadIdx.x & 31;
    const int wrp = threadIdx.x >> 5;
#pragma unroll
    for (int o = 16; o > 0; o >>= 1) {
        s += __shfl_down_sync(0xffffffffu, s, o);
        q += __shfl_down_sync(0xffffffffu, q, o);
    }
    if (lane == 0) {
        ss[wrp] = s;
        qs[wrp] = q;
    }
    __syncthreads();
    if (threadIdx.x == 0) {
        float S = 0.f, Q = 0.f;
#pragma unroll
        for (int w = 0; w < 8; w++) {
            S += ss[w];
            Q += qs[w];
        }
        const float inv_n = 1.0f / (float)NSITES;
        float mean = S * inv_n;
        float var = Q * inv_n - mean * mean;
        float scale = gamma[c] * rsqrtf(var + EPSV);
        sb[c] = scale;
        sb[32 + c] = beta[c] - mean * scale;
    }
}

// ---------------- in-place BN + ReLU (optionally tf32-truncating) -----------
template <int TRUNC>
__global__ __launch_bounds__(256) void bnrelu_kernel(float* __restrict__ Y,
                                                     const float* __restrict__ sb) {
    __shared__ float sc[32], bi[32];
    if (threadIdx.x < 32) {
        sc[threadIdx.x] = sb[threadIdx.x];
        bi[threadIdx.x] = sb[32 + threadIdx.x];
    }
    __syncthreads();
    const long long i = (long long)blockIdx.x * 256 + threadIdx.x;  // float4 idx
    float4* p = reinterpret_cast<float4*>(Y);
    float4 v = p[i];
    const int c0 = (int)((i * 4) & 31);
    v.x = fmaxf(0.f, fmaf(v.x, sc[c0 + 0], bi[c0 + 0]));
    v.y = fmaxf(0.f, fmaf(v.y, sc[c0 + 1], bi[c0 + 1]));
    v.z = fmaxf(0.f, fmaf(v.z, sc[c0 + 2], bi[c0 + 2]));
    v.w = fmaxf(0.f, fmaf(v.w, sc[c0 + 3], bi[c0 + 3]));
    if (TRUNC) {
        v.x = __uint_as_float(f2tf32(v.x));
        v.y = __uint_as_float(f2tf32(v.y));
        v.z = __uint_as_float(f2tf32(v.z));
        v.w = __uint_as_float(f2tf32(v.w));
    }
    p[i] = v;
}

// ---------------- launch ----------------------------------------------------
extern "C" void kernel_launch(void* const* d_in, const int* in_sizes, int n_in,
                              void* d_out, int out_size) {
    const float* feats = (const float*)d_in[0];
    const int* nm = (const int*)d_in[1];
    const float* W1 = (const float*)d_in[2];
    const float* gamma1 = (const float*)d_in[3];
    const float* beta1 = (const float*)d_in[4];
    const float* W2 = (const float*)d_in[5];
    const float* gamma2 = (const float*)d_in[6];
    const float* beta2 = (const float*)d_in[7];
    float* out = (float*)d_out;

    const int smem1 = (2 * 128 * 20 + 2 * 32 * 20) * 4;  // 25600 B
    const int smem2 = (2 * 128 * 36 + 2 * 32 * 36) * 4;  // 46080 B
    cudaFuncSetAttribute(conv_mma<16>,
                         cudaFuncAttributeMaxDynamicSharedMemorySize, smem1);
    cudaFuncSetAttribute(conv_mma<32>,
                         cudaFuncAttributeMaxDynamicSharedMemorySize, smem2);

    void* p;
    cudaGetSymbolAddress(&p, d_h1);
    float* h1 = (float*)p;
    cudaGetSymbolAddress(&p, d_xt);
    float* xt = (float*)p;
    cudaGetSymbolAddress(&p, d_wT1);
    float* wT1 = (float*)p;
    cudaGetSymbolAddress(&p, d_wT2);
    float* wT2 = (float*)p;
    cudaGetSymbolAddress(&p, d_sb1);
    float* sb1 = (float*)p;
    cudaGetSymbolAddress(&p, d_sb2);
    float* sb2 = (float*)p;

    const int ew_blocks = (int)(((long long)NSITES * 32 / 4) / 256);  // 31250
    const int tr_blocks = (NSITES + 255) / 256;                       // 3907
    const int px_blocks = (int)(((long long)NSITES * 16 / 4) / 256);  // 15625

    transpose_nm<<<tr_blocks, 256>>>(nm);
    prep_x<<<px_blocks, 256>>>(feats);
    prep_w<<<KVOL, 256>>>(W1, wT1, 16);
    prep_w<<<KVOL, 256>>>(W2, wT2, 32);

    conv_mma<16><<<NTILES, 128, smem1>>>(xt, wT1, h1);
    finalize_kernel<<<32, 256>>>(gamma1, beta1, sb1, NTILES);
    bnrelu_kernel<1><<<ew_blocks, 256>>>(h1, sb1);  // truncate for conv2 input

    conv_mma<32><<<NTILES, 128, smem2>>>(h1, wT2, out);
    finalize_kernel<<<32, 256>>>(gamma2, beta2, sb2, NTILES);
    bnrelu_kernel<0><<<ew_blocks, 256>>>(out, sb2);
}

// round 10
// speedup vs baseline: 2.8314x; 1.4039x over previous
#include <cuda_runtime.h>
#include <cstdint>

#define NSITES 1000000
#define KVOL 27
#define MTILE 128
#define NTILES ((NSITES + MTILE - 1) / MTILE)  // 7813
#define EPSV 1e-5f

// ---------------- scratch (device globals; no allocation allowed) ----------
__device__ float d_h1[(size_t)NSITES * 32];   // conv1 output / conv2 input
__device__ float d_xt[(size_t)NSITES * 16];   // tf32-truncated feats
__device__ int d_nmT[(size_t)KVOL * NSITES];  // transposed neighbor map
__device__ float d_wT1[KVOL * 16 * 32];       // WT[k][cout][cin], tf32-truncated
__device__ float d_wT2[KVOL * 32 * 32];
__device__ float d_part[(size_t)NTILES * 64]; // per-tile [sum(32), sumsq(32)]
__device__ float d_sb1[64];
__device__ float d_sb2[64];

// ---------------- helpers ---------------------------------------------------
static __device__ __forceinline__ uint32_t s2u(const void* p) {
    return (uint32_t)__cvta_generic_to_shared(p);
}
static __device__ __forceinline__ void cp16(uint32_t dst, const void* src,
                                            uint32_t srcsize) {
    asm volatile("cp.async.ca.shared.global [%0], [%1], 16, %2;\n" ::"r"(dst),
                 "l"(src), "r"(srcsize));
}
static __device__ __forceinline__ void cp_commit() {
    asm volatile("cp.async.commit_group;\n" ::: "memory");
}
template <int N>
static __device__ __forceinline__ void cp_wait() {
    asm volatile("cp.async.wait_group %0;\n" ::"n"(N) : "memory");
}
static __device__ __forceinline__ uint32_t f2tf32(float f) {
    uint32_t u;
    asm("cvt.rna.tf32.f32 %0, %1;" : "=r"(u) : "f"(f));
    return u;
}
// mma.sync m16n8k8 tf32: D(16x8,f32) += A(16x8,row) * B(8x8,col)
static __device__ __forceinline__ void mma_tf32(float* d, uint32_t a0,
                                                uint32_t a1, uint32_t a2,
                                                uint32_t a3, uint32_t b0,
                                                uint32_t b1) {
    asm volatile(
        "mma.sync.aligned.m16n8k8.row.col.f32.tf32.tf32.f32 "
        "{%0,%1,%2,%3},{%4,%5,%6,%7},{%8,%9},{%0,%1,%2,%3};"
        : "+f"(d[0]), "+f"(d[1]), "+f"(d[2]), "+f"(d[3])
        : "r"(a0), "r"(a1), "r"(a2), "r"(a3), "r"(b0), "r"(b1));
}
// ldmatrix x4: four 8-row x 16B submatrices
static __device__ __forceinline__ void ldsm4(uint32_t& r0, uint32_t& r1,
                                             uint32_t& r2, uint32_t& r3,
                                             uint32_t addr) {
    asm volatile(
        "ldmatrix.sync.aligned.m8n8.x4.shared.b16 {%0,%1,%2,%3}, [%4];"
        : "=r"(r0), "=r"(r1), "=r"(r2), "=r"(r3)
        : "r"(addr));
}

// ---------------- neighbor-map transpose ------------------------------------
__global__ __launch_bounds__(256) void transpose_nm(const int* __restrict__ nm) {
    __shared__ int tb[256 * KVOL];
    const int base = blockIdx.x * 256;
    const int nrows = min(256, NSITES - base);
    const int n = nrows * KVOL;
    const long long start = (long long)base * KVOL;
    for (int i = threadIdx.x; i < n; i += 256) tb[i] = nm[start + i];
    __syncthreads();
    const int t = threadIdx.x;
    if (base + t < NSITES) {
#pragma unroll
        for (int k = 0; k < KVOL; k++)
            d_nmT[(size_t)k * NSITES + base + t] = tb[t * KVOL + k];
    }
}

// ---------------- input truncation to tf32 ----------------------------------
__global__ __launch_bounds__(256) void prep_x(const float* __restrict__ X) {
    const long long i = (long long)blockIdx.x * 256 + threadIdx.x;  // float4 idx
    const float4 v = reinterpret_cast<const float4*>(X)[i];
    float4 o;
    o.x = __uint_as_float(f2tf32(v.x));
    o.y = __uint_as_float(f2tf32(v.y));
    o.z = __uint_as_float(f2tf32(v.z));
    o.w = __uint_as_float(f2tf32(v.w));
    reinterpret_cast<float4*>(d_xt)[i] = o;
}

// ---------------- weight transpose + truncate --------------------------------
// W[k][cin][cout] -> WT[k][cout][cin] (tf32-truncated)
__global__ void prep_w(const float* __restrict__ W, float* __restrict__ dst,
                       int cin) {
    const int k = blockIdx.x;
    for (int e = threadIdx.x; e < cin * 32; e += 256) {
        const int i = e / 32;
        const int c = e % 32;
        dst[((size_t)k * 32 + c) * cin + i] =
            __uint_as_float(f2tf32(W[((size_t)k * cin + i) * 32 + c]));
    }
}

// ---------------- mma.sync gather-conv ---------------------------------------
// 256 thr / 8 warps; warp w: sites [w*16, w*16+16) x all 32 couts (one m16
// tile). Halved per-warp work between barriers + 2x warps/SM -> latency
// exposure (the R9 bottleneck) is covered by concurrency.
template <int CIN>
__global__ __launch_bounds__(256) void conv_mma(const float* __restrict__ X,
                                                const float* __restrict__ WT,
                                                float* __restrict__ Y) {
    constexpr int NK = CIN / 8;    // K-steps per offset
    constexpr int CH = CIN / 4;    // 16B chunks per row
    constexpr int STR = CIN + 4;   // padded row stride (floats)
    constexpr int STR4 = STR * 4;  // bytes

    extern __shared__ float smem[];
    float* const A[2] = {smem, smem + 128 * STR};
    float* const B[2] = {smem + 256 * STR, smem + 256 * STR + 32 * STR};
    float* const red = smem;  // reused post-loop

    const int t = threadIdx.x;
    const int w = t >> 5;      // 0..7
    const int lane = t & 31;
    const int g = lane >> 2;   // groupID
    const int ti = lane & 3;   // thread-in-group
    const int siteBase = blockIdx.x * MTILE;

    // ldmatrix per-lane base offsets (bytes)
    const int lr = lane & 7;
    const int sel = lane >> 3;
    // A (m16 tile at rows w*16): a0..a3 = {r0-7,k0-3},{r8-15,k0-3},{r0-7,k4-7},{r8-15,k4-7}
    const uint32_t aoff =
        (uint32_t)((w * 16 + (sel & 1) * 8 + lr) * STR4 + ((sel & 2) ? 16 : 0));
    // B: submatrices {rows n8+0-7,k0-3},{n8,k4-7},{n8+8,k0-3},{n8+8,k4-7}
    const uint32_t boff =
        (uint32_t)((((sel >> 1) & 1) * 8 + lr) * STR4 + ((sel & 1) * 16));

    auto issue = [&](int k, int b) {
        // B: WT slice [32][CIN] -> padded rows (32*CH chunk ops over 256 thr)
        const float* wsrc = WT + (size_t)k * CIN * 32;
        if (t < 32 * CH) {
            const int row = t / CH;
            const int ch = t % CH;
            cp16(s2u(B[b] + row * STR + ch * 4), wsrc + t * 4, 16);
        }
        // A: gathered rows; 128*CH chunk ops over 256 thr
        const int* nmk = d_nmT + (size_t)k * NSITES;
#pragma unroll
        for (int f = t; f < 128 * CH; f += 256) {
            const int row = f / CH;
            const int ch = f % CH;
            const int gsite = siteBase + row;
            const int idx = (gsite < NSITES) ? nmk[gsite] : -1;
            const float* src = X + ((idx >= 0) ? (size_t)idx * CIN : 0) + ch * 4;
            cp16(s2u(A[b] + row * STR + ch * 4), src, (idx >= 0) ? 16u : 0u);
        }
    };

    float acc[4][4];
#pragma unroll
    for (int n = 0; n < 4; n++)
#pragma unroll
        for (int r = 0; r < 4; r++) acc[n][r] = 0.f;

    issue(0, 0);
    cp_commit();
    issue(1, 1);
    cp_commit();

#pragma unroll 1
    for (int k = 0; k < KVOL; k++) {
        const int b = k & 1;
        if (k < KVOL - 1)
            cp_wait<1>();
        else
            cp_wait<0>();
        __syncthreads();

        const uint32_t abase = s2u(A[b]) + aoff;
        const uint32_t bbase = s2u(B[b]) + boff;
#pragma unroll
        for (int ks = 0; ks < NK; ks++) {
            uint32_t bf[4][2];
            ldsm4(bf[0][0], bf[0][1], bf[1][0], bf[1][1],
                  bbase + (uint32_t)(ks * 32));
            ldsm4(bf[2][0], bf[2][1], bf[3][0], bf[3][1],
                  bbase + (uint32_t)(16 * STR4 + ks * 32));
            uint32_t a0, a1, a2, a3;
            ldsm4(a0, a1, a2, a3, abase + (uint32_t)(ks * 32));
#pragma unroll
            for (int n = 0; n < 4; n++)
                mma_tf32(acc[n], a0, a1, a2, a3, bf[n][0], bf[n][1]);
        }
        __syncthreads();
        if (k + 2 < KVOL) {
            issue(k + 2, b);
            cp_commit();
        }
    }

    // ---- store: thread holds rows {w*16+g, +8}, cols {n*8+2ti, +1} ----
#pragma unroll
    for (int rr = 0; rr < 2; rr++) {
        const int row = w * 16 + rr * 8 + g;
        const int site = siteBase + row;
        if (site < NSITES) {
            float* yr = Y + (size_t)site * 32 + 2 * ti;
#pragma unroll
            for (int n = 0; n < 4; n++) {
                float2 v = make_float2(acc[n][rr * 2], acc[n][rr * 2 + 1]);
                *reinterpret_cast<float2*>(yr + n * 8) = v;
            }
        }
    }

    // ---- BN partial stats (tail rows are zero by construction) ----
    float s[8], q[8];
#pragma unroll
    for (int i = 0; i < 8; i++) {
        s[i] = 0.f;
        q[i] = 0.f;
    }
#pragma unroll
    for (int n = 0; n < 4; n++)
#pragma unroll
        for (int rr = 0; rr < 2; rr++)
#pragma unroll
            for (int e = 0; e < 2; e++) {
                const float v = acc[n][rr * 2 + e];
                s[n * 2 + e] += v;
                q[n * 2 + e] += v * v;
            }
    // reduce across g (lanes differing in bits 2..4)
#pragma unroll
    for (int i = 0; i < 8; i++) {
#pragma unroll
        for (int o = 4; o <= 16; o <<= 1) {
            s[i] += __shfl_xor_sync(0xffffffffu, s[i], o);
            q[i] += __shfl_xor_sync(0xffffffffu, q[i], o);
        }
    }
    __syncthreads();  // smem free (stage buffers no longer needed)
    if (g == 0) {
#pragma unroll
        for (int i = 0; i < 8; i++) {
            const int col = (i / 2) * 8 + 2 * ti + (i % 2);
            red[w * 64 + col] = s[i];
            red[w * 64 + 32 + col] = q[i];
        }
    }
    __syncthreads();
    if (t < 64) {
        float ss = 0.f;
#pragma unroll
        for (int wi = 0; wi < 8; wi++) ss += red[wi * 64 + t];
        d_part[(size_t)blockIdx.x * 64 + t] = ss;
    }
}

// ---------------- finalize BN stats -> scale/bias --------------------------
__global__ void finalize_kernel(const float* __restrict__ gamma,
                                const float* __restrict__ beta,
                                float* __restrict__ sb, int nb) {
    const int c = blockIdx.x;  // 0..31
    float s = 0.f, q = 0.f;
    for (int b = threadIdx.x; b < nb; b += 256) {
        s += d_part[(size_t)b * 64 + c];
        q += d_part[(size_t)b * 64 + 32 + c];
    }
    __shared__ float ss[8], qs[8];
    const int lane = threadIdx.x & 31;
    const int wrp = threadIdx.x >> 5;
#pragma unroll
    for (int o = 16; o > 0; o >>= 1) {
        s += __shfl_down_sync(0xffffffffu, s, o);
        q += __shfl_down_sync(0xffffffffu, q, o);
    }
    if (lane == 0) {
        ss[wrp] = s;
        qs[wrp] = q;
    }
    __syncthreads();
    if (threadIdx.x == 0) {
        float S = 0.f, Q = 0.f;
#pragma unroll
        for (int w = 0; w < 8; w++) {
            S += ss[w];
            Q += qs[w];
        }
        const float inv_n = 1.0f / (float)NSITES;
        float mean = S * inv_n;
        float var = Q * inv_n - mean * mean;
        float scale = gamma[c] * rsqrtf(var + EPSV);
        sb[c] = scale;
        sb[32 + c] = beta[c] - mean * scale;
    }
}

// ---------------- in-place BN + ReLU (optionally tf32-truncating) -----------
template <int TRUNC>
__global__ __launch_bounds__(256) void bnrelu_kernel(float* __restrict__ Y,
                                                     const float* __restrict__ sb) {
    __shared__ float sc[32], bi[32];
    if (threadIdx.x < 32) {
        sc[threadIdx.x] = sb[threadIdx.x];
        bi[threadIdx.x] = sb[32 + threadIdx.x];
    }
    __syncthreads();
    const long long i = (long long)blockIdx.x * 256 + threadIdx.x;  // float4 idx
    float4* p = reinterpret_cast<float4*>(Y);
    float4 v = p[i];
    const int c0 = (int)((i * 4) & 31);
    v.x = fmaxf(0.f, fmaf(v.x, sc[c0 + 0], bi[c0 + 0]));
    v.y = fmaxf(0.f, fmaf(v.y, sc[c0 + 1], bi[c0 + 1]));
    v.z = fmaxf(0.f, fmaf(v.z, sc[c0 + 2], bi[c0 + 2]));
    v.w = fmaxf(0.f, fmaf(v.w, sc[c0 + 3], bi[c0 + 3]));
    if (TRUNC) {
        v.x = __uint_as_float(f2tf32(v.x));
        v.y = __uint_as_float(f2tf32(v.y));
        v.z = __uint_as_float(f2tf32(v.z));
        v.w = __uint_as_float(f2tf32(v.w));
    }
    p[i] = v;
}

// ---------------- launch ----------------------------------------------------
extern "C" void kernel_launch(void* const* d_in, const int* in_sizes, int n_in,
                              void* d_out, int out_size) {
    const float* feats = (const float*)d_in[0];
    const int* nm = (const int*)d_in[1];
    const float* W1 = (const float*)d_in[2];
    const float* gamma1 = (const float*)d_in[3];
    const float* beta1 = (const float*)d_in[4];
    const float* W2 = (const float*)d_in[5];
    const float* gamma2 = (const float*)d_in[6];
    const float* beta2 = (const float*)d_in[7];
    float* out = (float*)d_out;

    const int smem1 = (2 * 128 * 20 + 2 * 32 * 20) * 4;  // 25600 B
    const int smem2 = (2 * 128 * 36 + 2 * 32 * 36) * 4;  // 46080 B
    cudaFuncSetAttribute(conv_mma<16>,
                         cudaFuncAttributeMaxDynamicSharedMemorySize, smem1);
    cudaFuncSetAttribute(conv_mma<32>,
                         cudaFuncAttributeMaxDynamicSharedMemorySize, smem2);

    void* p;
    cudaGetSymbolAddress(&p, d_h1);
    float* h1 = (float*)p;
    cudaGetSymbolAddress(&p, d_xt);
    float* xt = (float*)p;
    cudaGetSymbolAddress(&p, d_wT1);
    float* wT1 = (float*)p;
    cudaGetSymbolAddress(&p, d_wT2);
    float* wT2 = (float*)p;
    cudaGetSymbolAddress(&p, d_sb1);
    float* sb1 = (float*)p;
    cudaGetSymbolAddress(&p, d_sb2);
    float* sb2 = (float*)p;

    const int ew_blocks = (int)(((long long)NSITES * 32 / 4) / 256);  // 31250
    const int tr_blocks = (NSITES + 255) / 256;                       // 3907
    const int px_blocks = (int)(((long long)NSITES * 16 / 4) / 256);  // 15625

    transpose_nm<<<tr_blocks, 256>>>(nm);
    prep_x<<<px_blocks, 256>>>(feats);
    prep_w<<<KVOL, 256>>>(W1, wT1, 16);
    prep_w<<<KVOL, 256>>>(W2, wT2, 32);

    conv_mma<16><<<NTILES, 256, smem1>>>(xt, wT1, h1);
    finalize_kernel<<<32, 256>>>(gamma1, beta1, sb1, NTILES);
    bnrelu_kernel<1><<<ew_blocks, 256>>>(h1, sb1);  // truncate for conv2 input

    conv_mma<32><<<NTILES, 256, smem2>>>(h1, wT2, out);
    finalize_kernel<<<32, 256>>>(gamma2, beta2, sb2, NTILES);
    bnrelu_kernel<0><<<ew_blocks, 256>>>(out, sb2);
}

// round 11
// speedup vs baseline: 4.0749x; 1.4392x over previous
#include <cuda_runtime.h>
#include <cuda_fp16.h>
#include <cstdint>

#define NSITES 1000000
#define KVOL 27
#define MTILE 128
#define NTILES ((NSITES + MTILE - 1) / MTILE)  // 7813
#define EPSV 1e-5f
#define NST 4  // pipeline stages

// ---------------- scratch (device globals; no allocation allowed) ----------
__device__ float d_h1[(size_t)NSITES * 32];     // conv1 output (fp32)
__device__ __half d_h1h[(size_t)NSITES * 32];   // BN1+ReLU output (half)
__device__ __half d_xh[(size_t)NSITES * 16];    // feats as half
__device__ int d_nmT[(size_t)KVOL * NSITES];    // transposed neighbor map
__device__ __half d_wT1[KVOL * 16 * 32];        // WT[k][cout][cin] half
__device__ __half d_wT2[KVOL * 32 * 32];
__device__ float d_part[(size_t)NTILES * 64];   // per-tile [sum(32), sumsq(32)]
__device__ float d_sb1[64];
__device__ float d_sb2[64];

// ---------------- helpers ---------------------------------------------------
static __device__ __forceinline__ uint32_t s2u(const void* p) {
    return (uint32_t)__cvta_generic_to_shared(p);
}
static __device__ __forceinline__ void cp16(uint32_t dst, const void* src,
                                            uint32_t srcsize) {
    asm volatile("cp.async.ca.shared.global [%0], [%1], 16, %2;\n" ::"r"(dst),
                 "l"(src), "r"(srcsize));
}
static __device__ __forceinline__ void cp_commit() {
    asm volatile("cp.async.commit_group;\n" ::: "memory");
}
template <int N>
static __device__ __forceinline__ void cp_wait() {
    asm volatile("cp.async.wait_group %0;\n" ::"n"(N) : "memory");
}
// mma.sync m16n8k16 fp16->fp32
static __device__ __forceinline__ void mma_f16(float* d, uint32_t a0,
                                               uint32_t a1, uint32_t a2,
                                               uint32_t a3, uint32_t b0,
                                               uint32_t b1) {
    asm volatile(
        "mma.sync.aligned.m16n8k16.row.col.f32.f16.f16.f32 "
        "{%0,%1,%2,%3},{%4,%5,%6,%7},{%8,%9},{%0,%1,%2,%3};"
        : "+f"(d[0]), "+f"(d[1]), "+f"(d[2]), "+f"(d[3])
        : "r"(a0), "r"(a1), "r"(a2), "r"(a3), "r"(b0), "r"(b1));
}
// ldmatrix x4: four 8-row x 16B submatrices
static __device__ __forceinline__ void ldsm4(uint32_t& r0, uint32_t& r1,
                                             uint32_t& r2, uint32_t& r3,
                                             uint32_t addr) {
    asm volatile(
        "ldmatrix.sync.aligned.m8n8.x4.shared.b16 {%0,%1,%2,%3}, [%4];"
        : "=r"(r0), "=r"(r1), "=r"(r2), "=r"(r3)
        : "r"(addr));
}

// ---------------- neighbor-map transpose ------------------------------------
__global__ __launch_bounds__(256) void transpose_nm(const int* __restrict__ nm) {
    __shared__ int tb[256 * KVOL];
    const int base = blockIdx.x * 256;
    const int nrows = min(256, NSITES - base);
    const int n = nrows * KVOL;
    const long long start = (long long)base * KVOL;
    for (int i = threadIdx.x; i < n; i += 256) tb[i] = nm[start + i];
    __syncthreads();
    const int t = threadIdx.x;
    if (base + t < NSITES) {
#pragma unroll
        for (int k = 0; k < KVOL; k++)
            d_nmT[(size_t)k * NSITES + base + t] = tb[t * KVOL + k];
    }
}

// ---------------- feats -> half ---------------------------------------------
__global__ __launch_bounds__(256) void prep_x(const float* __restrict__ X) {
    const long long i = (long long)blockIdx.x * 256 + threadIdx.x;  // float4 idx
    const float4 v = reinterpret_cast<const float4*>(X)[i];
    __half2* o = reinterpret_cast<__half2*>(d_xh);
    o[2 * i + 0] = __floats2half2_rn(v.x, v.y);
    o[2 * i + 1] = __floats2half2_rn(v.z, v.w);
}

// ---------------- weight transpose -> half ----------------------------------
// W[k][cin][cout] -> WT[k][cout][cin] half
__global__ void prep_w(const float* __restrict__ W, __half* __restrict__ dst,
                       int cin) {
    const int k = blockIdx.x;
    for (int e = threadIdx.x; e < cin * 32; e += 256) {
        const int i = e / 32;
        const int c = e % 32;
        dst[((size_t)k * 32 + c) * cin + i] =
            __float2half_rn(W[((size_t)k * cin + i) * 32 + c]);
    }
}

// ---------------- fp16 mma gather-conv --------------------------------------
// 256 thr / 8 warps; warp w: one m16 tile (16 sites) x 32 couts.
// 4-stage cp.async ring, depth-3 prefetch (dummy commits keep wait uniform).
template <int CIN>
__global__ __launch_bounds__(256) void conv_mma(const __half* __restrict__ X,
                                                const __half* __restrict__ WT,
                                                float* __restrict__ Y) {
    constexpr int NK = CIN / 16;     // K-steps per offset (2 or 1)
    constexpr int CHA = CIN / 8;     // 16B chunks per row (4 or 2)
    constexpr int STR = CIN + 8;     // padded row stride (halfs)
    constexpr int STRB = STR * 2;    // bytes
    constexpr int STAGE = 160 * STR; // halfs per stage (128 A rows + 32 B rows)

    extern __shared__ __half smem[];
    float* const red = reinterpret_cast<float*>(smem);  // reused post-loop

    const int t = threadIdx.x;
    const int w = t >> 5;     // 0..7
    const int lane = t & 31;
    const int g = lane >> 2;  // groupID
    const int ti = lane & 3;  // thread-in-group
    const int siteBase = blockIdx.x * MTILE;

    // ldmatrix per-lane base offsets (bytes)
    const int lr = lane & 7;
    const int sel = lane >> 3;
    // A m16 tile at rows w*16: subs {r0-7,k0-7},{r8-15,k0-7},{r0-7,k8-15},{r8-15,k8-15}
    const uint32_t aoff =
        (uint32_t)((w * 16 + (sel & 1) * 8 + lr) * STRB + ((sel & 2) ? 16 : 0));
    // B: subs {n0-7,k0-7},{n0-7,k8-15},{n8-15,k0-7},{n8-15,k8-15}
    const uint32_t boff =
        (uint32_t)((((sel >> 1) & 1) * 8 + lr) * STRB + (sel & 1) * 16);

    auto issue = [&](int k, int s) {
        __half* const As = smem + s * STAGE;
        __half* const Bs = As + 128 * STR;
        // B: WT slice [32][CIN] half -> padded rows
        const __half* wsrc = WT + (size_t)k * CIN * 32;
        if (t < 32 * CHA) {
            const int row = t / CHA;
            const int ch = t % CHA;
            cp16(s2u(Bs + row * STR + ch * 8), wsrc + t * 8, 16);
        }
        // A: gathered rows (CHA 16B chunks each), 128*CHA ops over 256 thr
        const int* nmk = d_nmT + (size_t)k * NSITES;
#pragma unroll
        for (int f = t; f < 128 * CHA; f += 256) {
            const int row = f / CHA;
            const int ch = f % CHA;
            const int gsite = siteBase + row;
            const int idx = (gsite < NSITES) ? nmk[gsite] : -1;
            const __half* src =
                X + ((idx >= 0) ? (size_t)idx * CIN : 0) + ch * 8;
            cp16(s2u(As + row * STR + ch * 8), src, (idx >= 0) ? 16u : 0u);
        }
    };

    float acc[4][4];
#pragma unroll
    for (int n = 0; n < 4; n++)
#pragma unroll
        for (int r = 0; r < 4; r++) acc[n][r] = 0.f;

    issue(0, 0);
    cp_commit();
    issue(1, 1);
    cp_commit();
    issue(2, 2);
    cp_commit();

#pragma unroll 1
    for (int k = 0; k < KVOL; k++) {
        cp_wait<2>();  // retires group k (dummy commits keep count uniform)
        __syncthreads();

        const __half* As = smem + (k & 3) * STAGE;
        const uint32_t abase = s2u(As) + aoff;
        const uint32_t bbase = s2u(As + 128 * STR) + boff;
#pragma unroll
        for (int ks = 0; ks < NK; ks++) {
            uint32_t bf[4][2];
            ldsm4(bf[0][0], bf[0][1], bf[1][0], bf[1][1],
                  bbase + (uint32_t)(ks * 32));
            ldsm4(bf[2][0], bf[2][1], bf[3][0], bf[3][1],
                  bbase + (uint32_t)(16 * STRB + ks * 32));
            uint32_t a0, a1, a2, a3;
            ldsm4(a0, a1, a2, a3, abase + (uint32_t)(ks * 32));
#pragma unroll
            for (int n = 0; n < 4; n++)
                mma_f16(acc[n], a0, a1, a2, a3, bf[n][0], bf[n][1]);
        }
        __syncthreads();
        if (k + 3 < KVOL) issue(k + 3, (k + 3) & 3);
        cp_commit();  // possibly-empty group: keeps wait<2> ledger exact
    }

    // ---- store: thread holds rows {w*16+g, +8}, cols {n*8+2ti, +1} ----
#pragma unroll
    for (int rr = 0; rr < 2; rr++) {
        const int row = w * 16 + rr * 8 + g;
        const int site = siteBase + row;
        if (site < NSITES) {
            float* yr = Y + (size_t)site * 32 + 2 * ti;
#pragma unroll
            for (int n = 0; n < 4; n++) {
                float2 v = make_float2(acc[n][rr * 2], acc[n][rr * 2 + 1]);
                *reinterpret_cast<float2*>(yr + n * 8) = v;
            }
        }
    }

    // ---- BN partial stats (tail rows are zero by construction) ----
    float s[8], q[8];
#pragma unroll
    for (int i = 0; i < 8; i++) {
        s[i] = 0.f;
        q[i] = 0.f;
    }
#pragma unroll
    for (int n = 0; n < 4; n++)
#pragma unroll
        for (int rr = 0; rr < 2; rr++)
#pragma unroll
            for (int e = 0; e < 2; e++) {
                const float v = acc[n][rr * 2 + e];
                s[n * 2 + e] += v;
                q[n * 2 + e] += v * v;
            }
#pragma unroll
    for (int i = 0; i < 8; i++) {
#pragma unroll
        for (int o = 4; o <= 16; o <<= 1) {
            s[i] += __shfl_xor_sync(0xffffffffu, s[i], o);
            q[i] += __shfl_xor_sync(0xffffffffu, q[i], o);
        }
    }
    __syncthreads();  // stage smem free for reduction
    if (g == 0) {
#pragma unroll
        for (int i = 0; i < 8; i++) {
            const int col = (i / 2) * 8 + 2 * ti + (i % 2);
            red[w * 64 + col] = s[i];
            red[w * 64 + 32 + col] = q[i];
        }
    }
    __syncthreads();
    if (t < 64) {
        float ss = 0.f;
#pragma unroll
        for (int wi = 0; wi < 8; wi++) ss += red[wi * 64 + t];
        d_part[(size_t)blockIdx.x * 64 + t] = ss;
    }
}

// ---------------- finalize BN stats -> scale/bias --------------------------
__global__ void finalize_kernel(const float* __restrict__ gamma,
                                const float* __restrict__ beta,
                                float* __restrict__ sb, int nb) {
    const int c = blockIdx.x;  // 0..31
    float s = 0.f, q = 0.f;
    for (int b = threadIdx.x; b < nb; b += 256) {
        s += d_part[(size_t)b * 64 + c];
        q += d_part[(size_t)b * 64 + 32 + c];
    }
    __shared__ float ss[8], qs[8];
    const int lane = threadIdx.x & 31;
    const int wrp = threadIdx.x >> 5;
#pragma unroll
    for (int o = 16; o > 0; o >>= 1) {
        s += __shfl_down_sync(0xffffffffu, s, o);
        q += __shfl_down_sync(0xffffffffu, q, o);
    }
    if (lane == 0) {
        ss[wrp] = s;
        qs[wrp] = q;
    }
    __syncthreads();
    if (threadIdx.x == 0) {
        float S = 0.f, Q = 0.f;
#pragma unroll
        for (int w = 0; w < 8; w++) {
            S += ss[w];
            Q += qs[w];
        }
        const float inv_n = 1.0f / (float)NSITES;
        float mean = S * inv_n;
        float var = Q * inv_n - mean * mean;
        float scale = gamma[c] * rsqrtf(var + EPSV);
        sb[c] = scale;
        sb[32 + c] = beta[c] - mean * scale;
    }
}

// ---------------- BN + ReLU; OUT_HALF writes half to HY, else fp32 in place -
template <int OUT_HALF>
__global__ __launch_bounds__(256) void bnrelu_kernel(float* __restrict__ Y,
                                                     __half* __restrict__ HY,
                                                     const float* __restrict__ sb) {
    __shared__ float sc[32], bi[32];
    if (threadIdx.x < 32) {
        sc[threadIdx.x] = sb[threadIdx.x];
        bi[threadIdx.x] = sb[32 + threadIdx.x];
    }
    __syncthreads();
    const long long i = (long long)blockIdx.x * 256 + threadIdx.x;  // float4 idx
    float4 v = reinterpret_cast<const float4*>(Y)[i];
    const int c0 = (int)((i * 4) & 31);
    v.x = fmaxf(0.f, fmaf(v.x, sc[c0 + 0], bi[c0 + 0]));
    v.y = fmaxf(0.f, fmaf(v.y, sc[c0 + 1], bi[c0 + 1]));
    v.z = fmaxf(0.f, fmaf(v.z, sc[c0 + 2], bi[c0 + 2]));
    v.w = fmaxf(0.f, fmaf(v.w, sc[c0 + 3], bi[c0 + 3]));
    if (OUT_HALF) {
        __half2* o = reinterpret_cast<__half2*>(HY);
        o[2 * i + 0] = __floats2half2_rn(v.x, v.y);
        o[2 * i + 1] = __floats2half2_rn(v.z, v.w);
    } else {
        reinterpret_cast<float4*>(Y)[i] = v;
    }
}

// ---------------- launch ----------------------------------------------------
extern "C" void kernel_launch(void* const* d_in, const int* in_sizes, int n_in,
                              void* d_out, int out_size) {
    const float* feats = (const float*)d_in[0];
    const int* nm = (const int*)d_in[1];
    const float* W1 = (const float*)d_in[2];
    const float* gamma1 = (const float*)d_in[3];
    const float* beta1 = (const float*)d_in[4];
    const float* W2 = (const float*)d_in[5];
    const float* gamma2 = (const float*)d_in[6];
    const float* beta2 = (const float*)d_in[7];
    float* out = (float*)d_out;

    const int smem1 = NST * 160 * (16 + 8) * 2;  // 30720 B
    const int smem2 = NST * 160 * (32 + 8) * 2;  // 51200 B
    cudaFuncSetAttribute(conv_mma<16>,
                         cudaFuncAttributeMaxDynamicSharedMemorySize, smem1);
    cudaFuncSetAttribute(conv_mma<32>,
                         cudaFuncAttributeMaxDynamicSharedMemorySize, smem2);

    void* p;
    cudaGetSymbolAddress(&p, d_h1);
    float* h1 = (float*)p;
    cudaGetSymbolAddress(&p, d_h1h);
    __half* h1h = (__half*)p;
    cudaGetSymbolAddress(&p, d_xh);
    __half* xh = (__half*)p;
    cudaGetSymbolAddress(&p, d_wT1);
    __half* wT1 = (__half*)p;
    cudaGetSymbolAddress(&p, d_wT2);
    __half* wT2 = (__half*)p;
    cudaGetSymbolAddress(&p, d_sb1);
    float* sb1 = (float*)p;
    cudaGetSymbolAddress(&p, d_sb2);
    float* sb2 = (float*)p;

    const int ew_blocks = (int)(((long long)NSITES * 32 / 4) / 256);  // 31250
    const int tr_blocks = (NSITES + 255) / 256;                       // 3907
    const int px_blocks = (int)(((long long)NSITES * 16 / 4) / 256);  // 15625

    transpose_nm<<<tr_blocks, 256>>>(nm);
    prep_x<<<px_blocks, 256>>>(feats);
    prep_w<<<KVOL, 256>>>(W1, wT1, 16);
    prep_w<<<KVOL, 256>>>(W2, wT2, 32);

    conv_mma<16><<<NTILES, 256, smem1>>>(xh, wT1, h1);
    finalize_kernel<<<32, 256>>>(gamma1, beta1, sb1, NTILES);
    bnrelu_kernel<1><<<ew_blocks, 256>>>(h1, h1h, sb1);  // -> half for conv2

    conv_mma<32><<<NTILES, 256, smem2>>>(h1h, wT2, out);
    finalize_kernel<<<32, 256>>>(gamma2, beta2, sb2, NTILES);
    bnrelu_kernel<0><<<ew_blocks, 256>>>(out, nullptr, sb2);
}